// round 1
// baseline (speedup 1.0000x reference)
#include <cuda_runtime.h>
#include <cstddef>

// ---------------- problem constants ----------------
#define TOTAL    65536          // B_GRAPHS * N_NODES
#define NGRAPH   16
#define NNODES   4096
#define INCH     256
#define HID      512
#define LN_EPS   1e-5f
#define QK_EPS   1e-6f
#define SPLITS   8              // split-K for kvs reduction

// ---------------- GEMM tiling ----------------
#define BM 128
#define BN 128
#define BK 16
#define LDS 132                 // BM + 4 padding (keeps 16B alignment: 132*4 % 16 == 0)

// ---------------- scratch (device globals; no allocation) ----------------
__device__ float g_h  [(size_t)TOTAL * HID];
__device__ float g_q  [(size_t)TOTAL * HID];
__device__ float g_k  [(size_t)TOTAL * HID];
__device__ float g_v  [(size_t)TOTAL * HID];
__device__ float g_t  [(size_t)TOTAL * HID];
__device__ float g_kvsp[(size_t)SPLITS * NGRAPH * HID * HID];
__device__ float g_kvs [(size_t)NGRAPH * HID * HID];
__device__ float g_ksp [(size_t)SPLITS * NGRAPH * HID];
__device__ float g_ks  [(size_t)NGRAPH * HID];
__device__ float g_den [(size_t)TOTAL];

// ---------------- helpers ----------------
__device__ __forceinline__ float wred(float v) {
#pragma unroll
    for (int o = 16; o; o >>= 1) v += __shfl_xor_sync(0xffffffffu, v, o);
    return v;
}

// Load a [BM rows x BK cols] tile from row-major G (ld = row stride, K-contiguous),
// storing transposed into S[k][m].
__device__ __forceinline__ void load_rowT(const float* __restrict__ G, int ld,
                                          size_t r0, int k0,
                                          float* __restrict__ S, int tid) {
    int row = tid >> 1;
    int kq  = (tid & 1) << 3;
    const float* src = G + (r0 + (size_t)row) * (size_t)ld + k0 + kq;
    float4 v0 = *(const float4*)(src);
    float4 v1 = *(const float4*)(src + 4);
    float* d = S + row;
    d[(kq + 0) * LDS] = v0.x; d[(kq + 1) * LDS] = v0.y;
    d[(kq + 2) * LDS] = v0.z; d[(kq + 3) * LDS] = v0.w;
    d[(kq + 4) * LDS] = v1.x; d[(kq + 5) * LDS] = v1.y;
    d[(kq + 6) * LDS] = v1.z; d[(kq + 7) * LDS] = v1.w;
}

// Load S[k][m] = G[(rowbase+k)*512 + c0 + m]  (m-contiguous: direct float4 copies)
__device__ __forceinline__ void load_direct(const float* __restrict__ G,
                                            size_t rowbase, int c0,
                                            float* __restrict__ S, int tid) {
#pragma unroll
    for (int t = 0; t < 2; ++t) {
        int idx = tid * 2 + t;
        int kk = idx >> 5, m4 = idx & 31;
        float4 v = *(const float4*)(G + (rowbase + (size_t)kk) * HID + c0 + m4 * 4);
        *(float4*)(S + kk * LDS + m4 * 4) = v;
    }
}

__device__ __forceinline__ void mma_tile(const float* __restrict__ As,
                                         const float* __restrict__ Bs,
                                         float (&acc)[8][8], int tx, int ty) {
#pragma unroll
    for (int kk = 0; kk < BK; ++kk) {
        float a[8], b[8];
        *(float4*)&a[0] = *(const float4*)(As + kk * LDS + ty * 8);
        *(float4*)&a[4] = *(const float4*)(As + kk * LDS + ty * 8 + 4);
        *(float4*)&b[0] = *(const float4*)(Bs + kk * LDS + tx * 8);
        *(float4*)&b[4] = *(const float4*)(Bs + kk * LDS + tx * 8 + 4);
#pragma unroll
        for (int i = 0; i < 8; ++i)
#pragma unroll
            for (int j = 0; j < 8; ++j)
                acc[i][j] = fmaf(a[i], b[j], acc[i][j]);
    }
}

// ---------------- C[m,n] = sum_k A[m,k] * W[n,k]  (+ optional bias[n]) ----------------
__global__ __launch_bounds__(256) void gemm_xw(const float* __restrict__ A,
                                               const float* __restrict__ W,
                                               const float* __restrict__ bias,
                                               float* __restrict__ C, int K) {
    __shared__ float As[BK * LDS];
    __shared__ float Bs[BK * LDS];
    int tid = threadIdx.x;
    int tx = tid & 15, ty = tid >> 4;
    size_t m0 = (size_t)blockIdx.y * BM;
    int n0 = blockIdx.x * BN;
    float acc[8][8] = {};
    for (int kt = 0; kt < K; kt += BK) {
        load_rowT(A, K, m0, kt, As, tid);
        load_rowT(W, K, (size_t)n0, kt, Bs, tid);
        __syncthreads();
        mma_tile(As, Bs, acc, tx, ty);
        __syncthreads();
    }
    float bv[8];
#pragma unroll
    for (int j = 0; j < 8; ++j) bv[j] = bias ? bias[n0 + tx * 8 + j] : 0.0f;
#pragma unroll
    for (int i = 0; i < 8; ++i) {
        size_t row = m0 + ty * 8 + i;
        float* dst = C + row * HID + n0 + tx * 8;
        float4 o0, o1;
        o0.x = acc[i][0] + bv[0]; o0.y = acc[i][1] + bv[1];
        o0.z = acc[i][2] + bv[2]; o0.w = acc[i][3] + bv[3];
        o1.x = acc[i][4] + bv[4]; o1.y = acc[i][5] + bv[5];
        o1.z = acc[i][6] + bv[6]; o1.w = acc[i][7] + bv[7];
        *(float4*)dst = o0; *(float4*)(dst + 4) = o1;
    }
}

// ---------------- kvs partial: Part[split][g][m,d] = sum_{n in split} k[n,m] v[n,d] ----------------
__global__ __launch_bounds__(256) void gemm_kv(const float* __restrict__ Kmat,
                                               const float* __restrict__ Vmat,
                                               float* __restrict__ Part) {
    __shared__ float As[BK * LDS];
    __shared__ float Bs[BK * LDS];
    int tid = threadIdx.x;
    int tx = tid & 15, ty = tid >> 4;
    int graph = blockIdx.z >> 3, split = blockIdx.z & 7;
    int m0 = blockIdx.y * BM, n0 = blockIdx.x * BN;
    size_t rowbase = (size_t)graph * NNODES + (size_t)split * (NNODES / SPLITS);
    float acc[8][8] = {};
    for (int kt = 0; kt < NNODES / SPLITS; kt += BK) {
        load_direct(Kmat, rowbase + kt, m0, As, tid);
        load_direct(Vmat, rowbase + kt, n0, Bs, tid);
        __syncthreads();
        mma_tile(As, Bs, acc, tx, ty);
        __syncthreads();
    }
    size_t base = ((size_t)(split * NGRAPH + graph)) * HID * HID;
#pragma unroll
    for (int i = 0; i < 8; ++i) {
        float* dst = Part + base + (size_t)(m0 + ty * 8 + i) * HID + n0 + tx * 8;
        float4 o0, o1;
        o0.x = acc[i][0]; o0.y = acc[i][1]; o0.z = acc[i][2]; o0.w = acc[i][3];
        o1.x = acc[i][4]; o1.y = acc[i][5]; o1.z = acc[i][6]; o1.w = acc[i][7];
        *(float4*)dst = o0; *(float4*)(dst + 4) = o1;
    }
}

__global__ void kvs_reduce(const float* __restrict__ Part, float* __restrict__ KVS) {
    size_t o = (size_t)blockIdx.x * blockDim.x + threadIdx.x;   // 16*512*512 total
    size_t graph = o >> 18;
    size_t r = o & ((1u << 18) - 1);
    float s = 0.0f;
#pragma unroll
    for (int sp = 0; sp < SPLITS; ++sp)
        s += Part[((size_t)(sp * NGRAPH) + graph) * HID * HID + r];
    KVS[o] = s;
}

// ---------------- attention output GEMM + fused epilogue ----------------
// t[n,d] = ((sum_m q[n,m] kvs[g][m,d] + N*v[n,d]) / den[n] + h[n,d]) * 0.5
__global__ __launch_bounds__(256) void gemm_num(const float* __restrict__ Q,
                                                const float* __restrict__ KVS,
                                                const float* __restrict__ V,
                                                const float* __restrict__ H,
                                                const float* __restrict__ den,
                                                float* __restrict__ Out) {
    __shared__ float As[BK * LDS];
    __shared__ float Bs[BK * LDS];
    int tid = threadIdx.x;
    int tx = tid & 15, ty = tid >> 4;
    size_t m0 = (size_t)blockIdx.y * BM;
    int n0 = blockIdx.x * BN;
    int graph = blockIdx.y >> 5;                       // 4096/128 = 32 tiles per graph
    const float* B = KVS + (size_t)graph * HID * HID;
    float acc[8][8] = {};
    for (int kt = 0; kt < HID; kt += BK) {
        load_rowT(Q, HID, m0, kt, As, tid);
        load_direct(B, (size_t)kt, n0, Bs, tid);
        __syncthreads();
        mma_tile(As, Bs, acc, tx, ty);
        __syncthreads();
    }
#pragma unroll
    for (int i = 0; i < 8; ++i) {
        size_t row = m0 + ty * 8 + i;
        float dinv = 1.0f / den[row];
        const float* vp = V + row * HID + n0 + tx * 8;
        const float* hp = H + row * HID + n0 + tx * 8;
        float4 v0 = *(const float4*)vp, v1 = *(const float4*)(vp + 4);
        float4 h0 = *(const float4*)hp, h1 = *(const float4*)(hp + 4);
        float4 o0, o1;
        o0.x = ((acc[i][0] + 4096.0f * v0.x) * dinv + h0.x) * 0.5f;
        o0.y = ((acc[i][1] + 4096.0f * v0.y) * dinv + h0.y) * 0.5f;
        o0.z = ((acc[i][2] + 4096.0f * v0.z) * dinv + h0.z) * 0.5f;
        o0.w = ((acc[i][3] + 4096.0f * v0.w) * dinv + h0.w) * 0.5f;
        o1.x = ((acc[i][4] + 4096.0f * v1.x) * dinv + h1.x) * 0.5f;
        o1.y = ((acc[i][5] + 4096.0f * v1.y) * dinv + h1.y) * 0.5f;
        o1.z = ((acc[i][6] + 4096.0f * v1.z) * dinv + h1.z) * 0.5f;
        o1.w = ((acc[i][7] + 4096.0f * v1.w) * dinv + h1.w) * 0.5f;
        float* dst = Out + row * HID + n0 + tx * 8;
        *(float4*)dst = o0; *(float4*)(dst + 4) = o1;
    }
}

// ---------------- LayerNorm + ReLU, one warp per 512-wide row ----------------
__global__ void ln_relu(const float* __restrict__ in, float* __restrict__ out,
                        const float* __restrict__ g, const float* __restrict__ b) {
    size_t warp = ((size_t)blockIdx.x * blockDim.x + threadIdx.x) >> 5;
    int lane = threadIdx.x & 31;
    const float4* src = (const float4*)(in + warp * HID);
    float4 v[4];
    float s = 0.0f, s2 = 0.0f;
#pragma unroll
    for (int c = 0; c < 4; ++c) {
        v[c] = src[lane + 32 * c];
        s  += v[c].x + v[c].y + v[c].z + v[c].w;
        s2 += v[c].x * v[c].x + v[c].y * v[c].y + v[c].z * v[c].z + v[c].w * v[c].w;
    }
    s = wred(s); s2 = wred(s2);
    float mu = s * (1.0f / HID);
    float var = s2 * (1.0f / HID) - mu * mu;
    float rstd = rsqrtf(var + LN_EPS);
    float4* dst = (float4*)(out + warp * HID);
#pragma unroll
    for (int c = 0; c < 4; ++c) {
        int i4 = lane + 32 * c;
        float4 gg = ((const float4*)g)[i4];
        float4 bb = ((const float4*)b)[i4];
        float4 o;
        o.x = fmaxf(0.0f, (v[c].x - mu) * rstd * gg.x + bb.x);
        o.y = fmaxf(0.0f, (v[c].y - mu) * rstd * gg.y + bb.y);
        o.z = fmaxf(0.0f, (v[c].z - mu) * rstd * gg.z + bb.z);
        o.w = fmaxf(0.0f, (v[c].w - mu) * rstd * gg.w + bb.w);
        dst[i4] = o;
    }
}

// ---------------- q/k: replace exact zeros with eps, L2-normalize row ----------------
__global__ void norm_qk(float* __restrict__ X) {
    size_t warp = ((size_t)blockIdx.x * blockDim.x + threadIdx.x) >> 5;
    int lane = threadIdx.x & 31;
    float4* p = (float4*)(X + warp * HID);
    float4 v[4];
    float s2 = 0.0f;
#pragma unroll
    for (int c = 0; c < 4; ++c) {
        v[c] = p[lane + 32 * c];
        if (v[c].x == 0.0f) v[c].x = QK_EPS;
        if (v[c].y == 0.0f) v[c].y = QK_EPS;
        if (v[c].z == 0.0f) v[c].z = QK_EPS;
        if (v[c].w == 0.0f) v[c].w = QK_EPS;
        s2 += v[c].x * v[c].x + v[c].y * v[c].y + v[c].z * v[c].z + v[c].w * v[c].w;
    }
    s2 = wred(s2);
    float rn = rsqrtf(s2);
#pragma unroll
    for (int c = 0; c < 4; ++c) {
        v[c].x *= rn; v[c].y *= rn; v[c].z *= rn; v[c].w *= rn;
        p[lane + 32 * c] = v[c];
    }
}

// ---------------- ks_sum partials: sum of normalized k over node chunks ----------------
__global__ void ksum_part(const float* __restrict__ Kmat, float* __restrict__ Part) {
    int graph = blockIdx.x >> 3, chunk = blockIdx.x & 7;
    int ch = threadIdx.x;                              // 512 threads
    size_t base = ((size_t)graph * NNODES + (size_t)chunk * (NNODES / SPLITS)) * HID + ch;
    float s = 0.0f;
#pragma unroll 8
    for (int r = 0; r < NNODES / SPLITS; ++r)
        s += Kmat[base + (size_t)r * HID];
    Part[(size_t)blockIdx.x * HID + ch] = s;
}

__global__ void ksum_reduce(const float* __restrict__ Part, float* __restrict__ KS) {
    int idx = blockIdx.x * blockDim.x + threadIdx.x;   // 16*512 total
    int graph = idx >> 9, ch = idx & 511;
    float s = 0.0f;
#pragma unroll
    for (int c = 0; c < SPLITS; ++c)
        s += Part[((size_t)(graph * SPLITS + c)) * HID + ch];
    KS[idx] = s;
}

// ---------------- denom[n] = q[n,:]·ks_sum[g] + N ----------------
__global__ void denom_kernel(const float* __restrict__ Q, const float* __restrict__ KS,
                             float* __restrict__ den) {
    size_t warp = ((size_t)blockIdx.x * blockDim.x + threadIdx.x) >> 5;
    int lane = threadIdx.x & 31;
    int graph = (int)(warp >> 12);                     // 4096 rows per graph
    const float4* qp = (const float4*)(Q + warp * HID);
    const float4* kp = (const float4*)(KS + (size_t)graph * HID);
    float s = 0.0f;
#pragma unroll
    for (int c = 0; c < 4; ++c) {
        float4 a = qp[lane + 32 * c];
        float4 b = kp[lane + 32 * c];
        s += a.x * b.x + a.y * b.y + a.z * b.z + a.w * b.w;
    }
    s = wred(s);
    if (lane == 0) den[warp] = s + (float)NNODES;
}

// ---------------- launch ----------------
extern "C" void kernel_launch(void* const* d_in, const int* in_sizes, int n_in,
                              void* d_out, int out_size) {
    const float* x     = (const float*)d_in[0];
    const float* fc0_w = (const float*)d_in[1];
    const float* fc0_b = (const float*)d_in[2];
    const float* ln_g[3] = { (const float*)d_in[3], (const float*)d_in[8],  (const float*)d_in[13] };
    const float* ln_b[3] = { (const float*)d_in[4], (const float*)d_in[9],  (const float*)d_in[14] };
    const float* qw[2] = { (const float*)d_in[5],  (const float*)d_in[10] };
    const float* kw[2] = { (const float*)d_in[6],  (const float*)d_in[11] };
    const float* vw[2] = { (const float*)d_in[7],  (const float*)d_in[12] };
    float* out = (float*)d_out;
    // batch (d_in[15]) is repeat(arange(16),4096): stable argsort == identity, rev_perm == identity.

    float *h, *q, *k, *v, *t, *kvsp, *kvs, *ksp, *ks, *den;
    cudaGetSymbolAddress((void**)&h,    g_h);
    cudaGetSymbolAddress((void**)&q,    g_q);
    cudaGetSymbolAddress((void**)&k,    g_k);
    cudaGetSymbolAddress((void**)&v,    g_v);
    cudaGetSymbolAddress((void**)&t,    g_t);
    cudaGetSymbolAddress((void**)&kvsp, g_kvsp);
    cudaGetSymbolAddress((void**)&kvs,  g_kvs);
    cudaGetSymbolAddress((void**)&ksp,  g_ksp);
    cudaGetSymbolAddress((void**)&ks,   g_ks);
    cudaGetSymbolAddress((void**)&den,  g_den);

    const dim3 gemm_grid(HID / BN, TOTAL / BM);        // (4, 512)
    const int  row_blocks = TOTAL / 8;                 // warp-per-row kernels, 256 thr = 8 warps

    // h = relu(LN(x @ fc0_w^T + b))
    gemm_xw<<<gemm_grid, 256>>>(x, fc0_w, fc0_b, t, INCH);
    ln_relu<<<row_blocks, 256>>>(t, h, ln_g[0], ln_b[0]);

    for (int l = 0; l < 2; ++l) {
        float* dst = (l == 1) ? out : h;
        gemm_xw<<<gemm_grid, 256>>>(h, qw[l], nullptr, q, HID);
        gemm_xw<<<gemm_grid, 256>>>(h, kw[l], nullptr, k, HID);
        gemm_xw<<<gemm_grid, 256>>>(h, vw[l], nullptr, v, HID);
        norm_qk<<<row_blocks, 256>>>(q);
        norm_qk<<<row_blocks, 256>>>(k);
        gemm_kv<<<dim3(HID / BN, HID / BM, NGRAPH * SPLITS), 256>>>(k, v, kvsp);
        kvs_reduce<<<(NGRAPH * HID * HID) / 256, 256>>>(kvsp, kvs);
        ksum_part<<<NGRAPH * SPLITS, HID>>>(k, ksp);
        ksum_reduce<<<(NGRAPH * HID) / 256, 256>>>(ksp, ks);
        denom_kernel<<<row_blocks, 256>>>(q, ks, den);
        gemm_num<<<gemm_grid, 256>>>(q, kvs, v, h, den, t);
        ln_relu<<<row_blocks, 256>>>(t, dst, ln_g[l + 1], ln_b[l + 1]);
    }
}

// round 3
// speedup vs baseline: 1.8324x; 1.8324x over previous
#include <cuda_runtime.h>
#include <cstdint>
#include <cstddef>

// ---------------- problem constants ----------------
#define TOTAL    65536          // B_GRAPHS * N_NODES
#define NGRAPH   16
#define NNODES   4096
#define INCH     256
#define HID      512
#define LN_EPS   1e-5f
#define QK_EPS   1e-6f
#define SPLITS   8              // for ksum partials
#define SK       4              // split-K for kv GEMM

// ---------------- GEMM tiling ----------------
#define BM 128
#define BN 128
#define BK 32
#define SST 136                 // smem row stride in floats (bank-conflict-free perm)
#define TILE_FLOATS (BK * SST)  // 4352
#define TILE_BYTES  (TILE_FLOATS * 4)   // 17408
#define SMEM_BYTES  (4 * TILE_BYTES)    // 69632 (A0,B0,A1,B1)

// epilogue modes
#define EPI_NONE 0
#define EPI_BIAS 1
#define EPI_ATT  2

// ---------------- scratch (device globals; no allocation) ----------------
__device__ float g_h  [(size_t)TOTAL * HID];
__device__ float g_q  [(size_t)TOTAL * HID];
__device__ float g_k  [(size_t)TOTAL * HID];
__device__ float g_v  [(size_t)TOTAL * HID];
__device__ float g_t  [(size_t)TOTAL * HID];
__device__ float g_kvp [(size_t)SK * NGRAPH * HID * HID];
__device__ float g_kvs [(size_t)NGRAPH * HID * HID];
__device__ float g_ksp [(size_t)SPLITS * NGRAPH * HID];
__device__ float g_ks  [(size_t)NGRAPH * HID];
__device__ float g_den [(size_t)TOTAL];

// ---------------- helpers ----------------
__device__ __forceinline__ uint32_t f2tf32(float f) {
    uint32_t u;
    asm("cvt.rna.tf32.f32 %0, %1;" : "=r"(u) : "f"(f));
    return u;
}

__device__ __forceinline__ void mma_tf32(float (&c)[4], const uint32_t (&a)[4],
                                         const uint32_t (&b)[2]) {
    asm volatile(
        "mma.sync.aligned.m16n8k8.row.col.f32.tf32.tf32.f32 "
        "{%0,%1,%2,%3}, {%4,%5,%6,%7}, {%8,%9}, {%0,%1,%2,%3};"
        : "+f"(c[0]), "+f"(c[1]), "+f"(c[2]), "+f"(c[3])
        : "r"(a[0]), "r"(a[1]), "r"(a[2]), "r"(a[3]), "r"(b[0]), "r"(b[1]));
}

// ---------------- gmem -> regs ----------------
// TR==0: tile(i,k) = G[(r0+i)*ld + k0+k]  (K contiguous)
// TR==1: tile(i,k) = G[(k0+k)*ld + r0+i]  (i contiguous)
template <int TR>
__device__ __forceinline__ void ldg_tile(const float* __restrict__ G, int ld,
                                         int r0, int k0, int tid, float4 (&r)[4]) {
    if (TR == 0) {
        const float4* src = (const float4*)(G + (size_t)(r0 + (tid >> 1)) * ld + k0) + (tid & 1) * 4;
#pragma unroll
        for (int j = 0; j < 4; ++j) r[j] = src[j];
    } else {
        const float4* src = (const float4*)(G + (size_t)(k0 + (tid >> 3)) * ld + r0) + (tid & 7);
#pragma unroll
        for (int j = 0; j < 4; ++j) r[j] = src[j * 8];
    }
}

// ---------------- regs -> smem (layout S[k][i], stride SST, tf32-converted) ----------------
template <int TR>
__device__ __forceinline__ void sts_tile(const float4 (&r)[4], uint32_t* __restrict__ S, int tid) {
    if (TR == 0) {
        int row = tid >> 1, kb = (tid & 1) * 16;
#pragma unroll
        for (int j = 0; j < 4; ++j) {
            int k = kb + j * 4;
            S[(k + 0) * SST + row] = f2tf32(r[j].x);
            S[(k + 1) * SST + row] = f2tf32(r[j].y);
            S[(k + 2) * SST + row] = f2tf32(r[j].z);
            S[(k + 3) * SST + row] = f2tf32(r[j].w);
        }
    } else {
        int k = tid >> 3, mq = (tid & 7) * 4;
#pragma unroll
        for (int j = 0; j < 4; ++j) {
            uint32_t* d = S + k * SST + mq + j * 32;
            uint4 o;
            o.x = f2tf32(r[j].x); o.y = f2tf32(r[j].y);
            o.z = f2tf32(r[j].z); o.w = f2tf32(r[j].w);
            *(uint4*)d = o;
        }
    }
}

// ---------------- compute one BK=32 chunk for this warp ----------------
__device__ __forceinline__ void compute_chunk(const uint32_t* __restrict__ As,
                                              const uint32_t* __restrict__ Bs,
                                              float (&acc)[4][4][4],
                                              int wm, int wn, int tr, int tq) {
#pragma unroll
    for (int s = 0; s < 4; ++s) {
        const int kb = s * 8;
        uint32_t afr[4][4], bfr[4][2];
#pragma unroll
        for (int mi = 0; mi < 4; ++mi) {
            int m = wm * 64 + mi * 16 + tr;
            afr[mi][0] = As[(kb + tq) * SST + m];
            afr[mi][1] = As[(kb + tq) * SST + m + 8];
            afr[mi][2] = As[(kb + tq + 4) * SST + m];
            afr[mi][3] = As[(kb + tq + 4) * SST + m + 8];
        }
#pragma unroll
        for (int ni = 0; ni < 4; ++ni) {
            int n = wn * 32 + ni * 8 + tr;
            bfr[ni][0] = Bs[(kb + tq) * SST + n];
            bfr[ni][1] = Bs[(kb + tq + 4) * SST + n];
        }
#pragma unroll
        for (int mi = 0; mi < 4; ++mi)
#pragma unroll
            for (int ni = 0; ni < 4; ++ni)
                mma_tf32(acc[mi][ni], afr[mi], bfr[ni]);
    }
}

// ================= tf32 mma.sync GEMM, 128x128 CTA tile, double-buffered =================
// C[m0+i, n0+j] (+epilogue) = sum_k A(i,k) * B(j,k)
// blockIdx.z decomposed: graph = z & 15, split = z >> 4.
template <int TA, int TB, int EPI>
__global__ __launch_bounds__(256)
void mm_tc(const float* __restrict__ A, const float* __restrict__ B,
           float* __restrict__ C,
           const float* __restrict__ P1, const float* __restrict__ P2,
           const float* __restrict__ P3,
           int Kdim, int lda, int ldb, int ldc,
           size_t aG, size_t aS, size_t bG, size_t bS, size_t cG, size_t cS,
           int mZ) {
    extern __shared__ char smem[];
    uint32_t* Sb[2][2];
    Sb[0][0] = (uint32_t*)smem;
    Sb[0][1] = Sb[0][0] + TILE_FLOATS;
    Sb[1][0] = Sb[0][1] + TILE_FLOATS;
    Sb[1][1] = Sb[1][0] + TILE_FLOATS;

    const int tid = threadIdx.x;
    const int wid = tid >> 5, lane = tid & 31;
    const int wm = wid & 1, wn = wid >> 1;
    const int tr = lane >> 2, tq = lane & 3;

    const int z = blockIdx.z;
    const int graph = z & (NGRAPH - 1);
    const int split = z >> 4;
    A += aG * graph + aS * split;
    B += bG * graph + bS * split;
    C += cG * graph + cS * split;
    const int m0 = blockIdx.y * BM + mZ * graph;
    const int n0 = blockIdx.x * BN;

    float acc[4][4][4] = {};
    float4 ra[4], rb[4];

    // prologue: stage 0
    ldg_tile<TA>(A, lda, m0, 0, tid, ra);
    ldg_tile<TB>(B, ldb, n0, 0, tid, rb);
    sts_tile<TA>(ra, Sb[0][0], tid);
    sts_tile<TB>(rb, Sb[0][1], tid);
    __syncthreads();

    const int nK = Kdim / BK;
    for (int kt = 0; kt < nK; ++kt) {
        int cur = kt & 1;
        if (kt + 1 < nK) {
            ldg_tile<TA>(A, lda, m0, (kt + 1) * BK, tid, ra);
            ldg_tile<TB>(B, ldb, n0, (kt + 1) * BK, tid, rb);
        }
        compute_chunk(Sb[cur][0], Sb[cur][1], acc, wm, wn, tr, tq);
        if (kt + 1 < nK) {
            sts_tile<TA>(ra, Sb[cur ^ 1][0], tid);
            sts_tile<TB>(rb, Sb[cur ^ 1][1], tid);
        }
        __syncthreads();
    }

    // ---------------- epilogue ----------------
#pragma unroll
    for (int mi = 0; mi < 4; ++mi) {
        int rbase = m0 + wm * 64 + mi * 16 + tr;
#pragma unroll
        for (int half = 0; half < 2; ++half) {
            size_t row = (size_t)rbase + half * 8;
            float dinv = 0.0f;
            if (EPI == EPI_ATT) dinv = 1.0f / P3[row];
#pragma unroll
            for (int ni = 0; ni < 4; ++ni) {
                int col = n0 + wn * 32 + ni * 8 + tq * 2;
                float c0 = acc[mi][ni][half * 2 + 0];
                float c1 = acc[mi][ni][half * 2 + 1];
                float* dst = C + row * (size_t)ldc + col;
                if (EPI == EPI_NONE) {
                    float2 o = {c0, c1};
                    *(float2*)dst = o;
                } else if (EPI == EPI_BIAS) {
                    float2 bv = *(const float2*)(P1 + col);
                    float2 o = {c0 + bv.x, c1 + bv.y};
                    *(float2*)dst = o;
                } else {
                    float2 vv = *(const float2*)(P1 + row * HID + col);
                    float2 hh = *(const float2*)(P2 + row * HID + col);
                    float2 o;
                    o.x = ((c0 + 4096.0f * vv.x) * dinv + hh.x) * 0.5f;
                    o.y = ((c1 + 4096.0f * vv.y) * dinv + hh.y) * 0.5f;
                    *(float2*)dst = o;
                }
            }
        }
    }
}

// ================= elementwise kernels =================
__device__ __forceinline__ float wred(float v) {
#pragma unroll
    for (int o = 16; o; o >>= 1) v += __shfl_xor_sync(0xffffffffu, v, o);
    return v;
}

__global__ void ln_relu(const float* __restrict__ in, float* __restrict__ out,
                        const float* __restrict__ g, const float* __restrict__ b) {
    size_t warp = ((size_t)blockIdx.x * blockDim.x + threadIdx.x) >> 5;
    int lane = threadIdx.x & 31;
    const float4* src = (const float4*)(in + warp * HID);
    float4 v[4];
    float s = 0.0f, s2 = 0.0f;
#pragma unroll
    for (int c = 0; c < 4; ++c) {
        v[c] = src[lane + 32 * c];
        s  += v[c].x + v[c].y + v[c].z + v[c].w;
        s2 += v[c].x * v[c].x + v[c].y * v[c].y + v[c].z * v[c].z + v[c].w * v[c].w;
    }
    s = wred(s); s2 = wred(s2);
    float mu = s * (1.0f / HID);
    float var = s2 * (1.0f / HID) - mu * mu;
    float rstd = rsqrtf(var + LN_EPS);
    float4* dst = (float4*)(out + warp * HID);
#pragma unroll
    for (int c = 0; c < 4; ++c) {
        int i4 = lane + 32 * c;
        float4 gg = ((const float4*)g)[i4];
        float4 bb = ((const float4*)b)[i4];
        float4 o;
        o.x = fmaxf(0.0f, (v[c].x - mu) * rstd * gg.x + bb.x);
        o.y = fmaxf(0.0f, (v[c].y - mu) * rstd * gg.y + bb.y);
        o.z = fmaxf(0.0f, (v[c].z - mu) * rstd * gg.z + bb.z);
        o.w = fmaxf(0.0f, (v[c].w - mu) * rstd * gg.w + bb.w);
        dst[i4] = o;
    }
}

__global__ void norm_qk(float* __restrict__ X) {
    size_t warp = ((size_t)blockIdx.x * blockDim.x + threadIdx.x) >> 5;
    int lane = threadIdx.x & 31;
    float4* p = (float4*)(X + warp * HID);
    float4 v[4];
    float s2 = 0.0f;
#pragma unroll
    for (int c = 0; c < 4; ++c) {
        v[c] = p[lane + 32 * c];
        if (v[c].x == 0.0f) v[c].x = QK_EPS;
        if (v[c].y == 0.0f) v[c].y = QK_EPS;
        if (v[c].z == 0.0f) v[c].z = QK_EPS;
        if (v[c].w == 0.0f) v[c].w = QK_EPS;
        s2 += v[c].x * v[c].x + v[c].y * v[c].y + v[c].z * v[c].z + v[c].w * v[c].w;
    }
    s2 = wred(s2);
    float rn = rsqrtf(s2);
#pragma unroll
    for (int c = 0; c < 4; ++c) {
        v[c].x *= rn; v[c].y *= rn; v[c].z *= rn; v[c].w *= rn;
        p[lane + 32 * c] = v[c];
    }
}

__global__ void kvs_reduce(const float* __restrict__ Part, float* __restrict__ KVS) {
    size_t o = (size_t)blockIdx.x * blockDim.x + threadIdx.x;   // 16*512*512
    size_t graph = o >> 18;
    size_t r = o & ((1u << 18) - 1);
    float s = 0.0f;
#pragma unroll
    for (int sp = 0; sp < SK; ++sp)
        s += Part[((size_t)sp * NGRAPH + graph) * HID * HID + r];
    KVS[o] = s;
}

__global__ void ksum_part(const float* __restrict__ Kmat, float* __restrict__ Part) {
    int graph = blockIdx.x >> 3, chunk = blockIdx.x & 7;
    int ch = threadIdx.x;
    size_t base = ((size_t)graph * NNODES + (size_t)chunk * (NNODES / SPLITS)) * HID + ch;
    float s = 0.0f;
#pragma unroll 8
    for (int r = 0; r < NNODES / SPLITS; ++r)
        s += Kmat[base + (size_t)r * HID];
    Part[(size_t)blockIdx.x * HID + ch] = s;
}

__global__ void ksum_reduce(const float* __restrict__ Part, float* __restrict__ KS) {
    int idx = blockIdx.x * blockDim.x + threadIdx.x;
    int graph = idx >> 9, ch = idx & 511;
    float s = 0.0f;
#pragma unroll
    for (int c = 0; c < SPLITS; ++c)
        s += Part[((size_t)(graph * SPLITS + c)) * HID + ch];
    KS[idx] = s;
}

__global__ void denom_kernel(const float* __restrict__ Q, const float* __restrict__ KS,
                             float* __restrict__ den) {
    size_t warp = ((size_t)blockIdx.x * blockDim.x + threadIdx.x) >> 5;
    int lane = threadIdx.x & 31;
    int graph = (int)(warp >> 12);
    const float4* qp = (const float4*)(Q + warp * HID);
    const float4* kp = (const float4*)(KS + (size_t)graph * HID);
    float s = 0.0f;
#pragma unroll
    for (int c = 0; c < 4; ++c) {
        float4 a = qp[lane + 32 * c];
        float4 b = kp[lane + 32 * c];
        s += a.x * b.x + a.y * b.y + a.z * b.z + a.w * b.w;
    }
    s = wred(s);
    if (lane == 0) den[warp] = s + (float)NNODES;
}

// ================= launch =================
extern "C" void kernel_launch(void* const* d_in, const int* in_sizes, int n_in,
                              void* d_out, int out_size) {
    const float* x     = (const float*)d_in[0];
    const float* fc0_w = (const float*)d_in[1];
    const float* fc0_b = (const float*)d_in[2];
    const float* ln_g[3] = { (const float*)d_in[3], (const float*)d_in[8],  (const float*)d_in[13] };
    const float* ln_b[3] = { (const float*)d_in[4], (const float*)d_in[9],  (const float*)d_in[14] };
    const float* qw[2] = { (const float*)d_in[5],  (const float*)d_in[10] };
    const float* kw[2] = { (const float*)d_in[6],  (const float*)d_in[11] };
    const float* vw[2] = { (const float*)d_in[7],  (const float*)d_in[12] };
    float* out = (float*)d_out;
    // batch = repeat(arange(16), 4096): argsort and rev_perm are identities.

    float *h, *q, *k, *v, *t, *kvp, *kvs, *ksp, *ks, *den;
    cudaGetSymbolAddress((void**)&h,   g_h);
    cudaGetSymbolAddress((void**)&q,   g_q);
    cudaGetSymbolAddress((void**)&k,   g_k);
    cudaGetSymbolAddress((void**)&v,   g_v);
    cudaGetSymbolAddress((void**)&t,   g_t);
    cudaGetSymbolAddress((void**)&kvp, g_kvp);
    cudaGetSymbolAddress((void**)&kvs, g_kvs);
    cudaGetSymbolAddress((void**)&ksp, g_ksp);
    cudaGetSymbolAddress((void**)&ks,  g_ks);
    cudaGetSymbolAddress((void**)&den, g_den);

    cudaFuncSetAttribute((const void*)mm_tc<0,0,EPI_BIAS>,
                         cudaFuncAttributeMaxDynamicSharedMemorySize, SMEM_BYTES);
    cudaFuncSetAttribute((const void*)mm_tc<0,0,EPI_NONE>,
                         cudaFuncAttributeMaxDynamicSharedMemorySize, SMEM_BYTES);
    cudaFuncSetAttribute((const void*)mm_tc<1,1,EPI_NONE>,
                         cudaFuncAttributeMaxDynamicSharedMemorySize, SMEM_BYTES);
    cudaFuncSetAttribute((const void*)mm_tc<0,1,EPI_ATT>,
                         cudaFuncAttributeMaxDynamicSharedMemorySize, SMEM_BYTES);

    const dim3 big_grid(HID / BN, TOTAL / BM, 1);   // (4, 512)
    const int  row_blocks = TOTAL / 8;

    // h = relu(LN(x @ fc0_w^T + b))
    mm_tc<0,0,EPI_BIAS><<<big_grid, 256, SMEM_BYTES>>>(
        x, fc0_w, t, fc0_b, nullptr, nullptr, INCH, INCH, INCH, HID,
        0, 0, 0, 0, 0, 0, 0);
    ln_relu<<<row_blocks, 256>>>(t, h, ln_g[0], ln_b[0]);

    for (int l = 0; l < 2; ++l) {
        float* dst = (l == 1) ? out : h;
        mm_tc<0,0,EPI_NONE><<<big_grid, 256, SMEM_BYTES>>>(
            h, qw[l], q, nullptr, nullptr, nullptr, HID, HID, HID, HID,
            0, 0, 0, 0, 0, 0, 0);
        mm_tc<0,0,EPI_NONE><<<big_grid, 256, SMEM_BYTES>>>(
            h, kw[l], k, nullptr, nullptr, nullptr, HID, HID, HID, HID,
            0, 0, 0, 0, 0, 0, 0);
        mm_tc<0,0,EPI_NONE><<<big_grid, 256, SMEM_BYTES>>>(
            h, vw[l], v, nullptr, nullptr, nullptr, HID, HID, HID, HID,
            0, 0, 0, 0, 0, 0, 0);
        norm_qk<<<row_blocks, 256>>>(q);
        norm_qk<<<row_blocks, 256>>>(k);
        // kvp[split][g][m,d] = sum_{n in split} k[g,n,m] * v[g,n,d]
        mm_tc<1,1,EPI_NONE><<<dim3(HID / BN, HID / BM, NGRAPH * SK), 256, SMEM_BYTES>>>(
            k, v, kvp, nullptr, nullptr, nullptr, NNODES / SK, HID, HID, HID,
            (size_t)NNODES * HID, (size_t)(NNODES / SK) * HID,
            (size_t)NNODES * HID, (size_t)(NNODES / SK) * HID,
            (size_t)HID * HID, (size_t)NGRAPH * HID * HID, 0);
        kvs_reduce<<<(NGRAPH * HID * HID) / 256, 256>>>(kvp, kvs);
        ksum_part<<<NGRAPH * SPLITS, HID>>>(k, ksp);
        ksum_reduce<<<(NGRAPH * HID) / 256, 256>>>(ksp, ks);
        denom_kernel<<<row_blocks, 256>>>(q, ks, den);
        // t = ((q @ kvs + N*v)/den + h)/2
        mm_tc<0,1,EPI_ATT><<<dim3(HID / BN, NNODES / BM, NGRAPH), 256, SMEM_BYTES>>>(
            q, kvs, t, v, h, den, HID, HID, HID, HID,
            0, 0, (size_t)HID * HID, 0, 0, 0, NNODES);
        ln_relu<<<row_blocks, 256>>>(t, dst, ln_g[l + 1], ln_b[l + 1]);
    }
}

// round 4
// speedup vs baseline: 2.6656x; 1.4547x over previous
#include <cuda_runtime.h>
#include <cstdint>
#include <cstddef>

// ---------------- problem constants ----------------
#define TOTAL    65536          // B_GRAPHS * N_NODES
#define NGRAPH   16
#define NNODES   4096
#define INCH     256
#define HID      512
#define LN_EPS   1e-5f
#define QK_EPS   1e-6f
#define SPLITS   8              // for ksum partials
#define SK       4              // split-K for kv GEMM

// ---------------- GEMM tiling ----------------
#define BM 128
#define BN 128
#define BK 32
// TR0 tile: 128 rows x 36 floats (stride 36 = 144B, 16B-aligned, ldmatrix-friendly)
// TR1 tile: 32 rows x 136 floats (stride 136, bank-conflict-free LDS)
#define SLOT_BYTES  18432               // max(128*36*4, 32*136*4) = 18432
#define STAGE_BYTES (2 * SLOT_BYTES)    // A slot + B slot
#define NSTAGE 3
#define SMEM_BYTES (NSTAGE * STAGE_BYTES)   // 110592

// epilogue modes
#define EPI_NONE 0
#define EPI_BIAS 1
#define EPI_ATT  2

// ---------------- scratch (device globals; no allocation) ----------------
__device__ float g_h  [(size_t)TOTAL * HID];
__device__ float g_q  [(size_t)TOTAL * HID];
__device__ float g_k  [(size_t)TOTAL * HID];
__device__ float g_v  [(size_t)TOTAL * HID];
__device__ float g_t  [(size_t)TOTAL * HID];
__device__ float g_xr [(size_t)TOTAL * INCH];
__device__ float g_wr [(size_t)(HID * INCH + 6 * HID * HID)];
__device__ float g_kvp [(size_t)SK * NGRAPH * HID * HID];
__device__ float g_kvs [(size_t)NGRAPH * HID * HID];
__device__ float g_ksp [(size_t)SPLITS * NGRAPH * HID];
__device__ float g_ks  [(size_t)NGRAPH * HID];
__device__ float g_den [(size_t)TOTAL];

// ---------------- helpers ----------------
__device__ __forceinline__ uint32_t smem_to_u32(const void* p) {
    uint32_t a;
    asm("{ .reg .u64 t; cvta.to.shared.u64 t, %1; cvt.u32.u64 %0, t; }" : "=r"(a) : "l"(p));
    return a;
}
__device__ __forceinline__ uint32_t f2tf32(float f) {
    uint32_t u;
    asm("cvt.rna.tf32.f32 %0, %1;" : "=r"(u) : "f"(f));
    return u;
}
__device__ __forceinline__ float roundtf(float f) { return __uint_as_float(f2tf32(f)); }

__device__ __forceinline__ void mma_tf32(float (&c)[4], const uint32_t (&a)[4],
                                         const uint32_t (&b)[2]) {
    asm volatile(
        "mma.sync.aligned.m16n8k8.row.col.f32.tf32.tf32.f32 "
        "{%0,%1,%2,%3}, {%4,%5,%6,%7}, {%8,%9}, {%0,%1,%2,%3};"
        : "+f"(c[0]), "+f"(c[1]), "+f"(c[2]), "+f"(c[3])
        : "r"(a[0]), "r"(a[1]), "r"(a[2]), "r"(a[3]), "r"(b[0]), "r"(b[1]));
}
__device__ __forceinline__ void ldsm_x4(uint32_t (&r)[4], uint32_t addr) {
    asm volatile("ldmatrix.sync.aligned.m8n8.x4.shared.b16 {%0,%1,%2,%3}, [%4];"
        : "=r"(r[0]), "=r"(r[1]), "=r"(r[2]), "=r"(r[3]) : "r"(addr));
}
__device__ __forceinline__ uint32_t lds32(uint32_t addr) {
    uint32_t v;
    asm volatile("ld.shared.b32 %0, [%1];" : "=r"(v) : "r"(addr));
    return v;
}
__device__ __forceinline__ void cpa16(uint32_t dst, const float* src) {
    asm volatile("cp.async.cg.shared.global [%0], [%1], 16;" :: "r"(dst), "l"(src) : "memory");
}
#define CP_COMMIT() asm volatile("cp.async.commit_group;" ::: "memory")

// ================= tf32 mma.sync GEMM, 128x128 tile, 3-stage cp.async =================
// C[m0+i, n0+j] (+epilogue) = sum_k A(i,k) * B(j,k)
// TR==0: operand K-contiguous in gmem (tile S[row][k], stride 36, ldmatrix frags)
// TR==1: operand MN-contiguous in gmem (tile S[k][row], stride 136, LDS.32 frags)
// All operand values must already be tf32-representable fp32 (pre-rounded).
template <int TA, int TB, int EPI, int RND>
__global__ __launch_bounds__(256, 2)
void mm_tc(const float* __restrict__ A, const float* __restrict__ B,
           float* __restrict__ C,
           const float* __restrict__ P1, const float* __restrict__ P2,
           const float* __restrict__ P3,
           int Kdim, int lda, int ldb, int ldc,
           size_t aG, size_t aS, size_t bG, size_t bS, size_t cG, size_t cS,
           int mZ) {
    extern __shared__ char smem[];
    const uint32_t sb = smem_to_u32(smem);

    const int tid = threadIdx.x;
    const int wid = tid >> 5, lane = tid & 31;
    const int wm = wid & 1, wn = wid >> 1;
    const int tr = lane >> 2, tq = lane & 3;
    const int g8 = lane >> 3, rl = lane & 7;

    const int z = blockIdx.z;
    const int graph = z & (NGRAPH - 1);
    const int split = z >> 4;
    A += aG * graph + aS * split;
    B += bG * graph + bS * split;
    C += cG * graph + cS * split;
    const int m0 = blockIdx.y * BM + mZ * graph;
    const int n0 = blockIdx.x * BN;

    // per-lane relative fragment offsets (bytes, within a tile slot)
    uint32_t aRel, bRel;
    if (TA == 0) aRel = (uint32_t)(((wm * 64 + (g8 & 1) * 8 + rl) * 36 + (g8 >> 1) * 4) * 4);
    else         aRel = (uint32_t)((tq * 136 + wm * 64 + tr) * 4);
    if (TB == 0) bRel = (uint32_t)(((wn * 32 + (g8 >> 1) * 8 + rl) * 36 + (g8 & 1) * 4) * 4);
    else         bRel = (uint32_t)((tq * 136 + wn * 32 + tr) * 4);

    // cp.async issue for one pipeline stage
    auto issue = [&](int stage, int ktile) {
        const int k0 = ktile * BK;
        uint32_t slotA = sb + (uint32_t)stage * STAGE_BYTES;
        uint32_t slotB = slotA + SLOT_BYTES;
        if (TA == 0) {
            int row = tid >> 1, cb = (tid & 1) * 16;      // floats
            const float* s = A + (size_t)(m0 + row) * lda + k0 + cb;
            uint32_t d = slotA + (uint32_t)((row * 36 + cb) * 4);
#pragma unroll
            for (int j = 0; j < 4; ++j) cpa16(d + j * 16, s + j * 4);
        } else {
            int kr = tid >> 3, c = (tid & 7) * 4;
            const float* s = A + (size_t)(k0 + kr) * lda + m0 + c;
            uint32_t d = slotA + (uint32_t)((kr * 136 + c) * 4);
#pragma unroll
            for (int j = 0; j < 4; ++j) cpa16(d + j * 128, s + j * 32);
        }
        if (TB == 0) {
            int row = tid >> 1, cb = (tid & 1) * 16;
            const float* s = B + (size_t)(n0 + row) * ldb + k0 + cb;
            uint32_t d = slotB + (uint32_t)((row * 36 + cb) * 4);
#pragma unroll
            for (int j = 0; j < 4; ++j) cpa16(d + j * 16, s + j * 4);
        } else {
            int kr = tid >> 3, c = (tid & 7) * 4;
            const float* s = B + (size_t)(k0 + kr) * ldb + n0 + c;
            uint32_t d = slotB + (uint32_t)((kr * 136 + c) * 4);
#pragma unroll
            for (int j = 0; j < 4; ++j) cpa16(d + j * 128, s + j * 32);
        }
    };

    float acc[4][4][4] = {};

    // prologue: stages 0, 1
    issue(0, 0); CP_COMMIT();
    issue(1, 1); CP_COMMIT();

    const int nK = Kdim / BK;
    for (int kt = 0; kt < nK; ++kt) {
        if (kt + 2 < nK) {
            issue((kt + 2) % NSTAGE, kt + 2); CP_COMMIT();
            asm volatile("cp.async.wait_group 2;" ::: "memory");
        } else if (kt + 1 < nK) {
            asm volatile("cp.async.wait_group 1;" ::: "memory");
        } else {
            asm volatile("cp.async.wait_group 0;" ::: "memory");
        }
        __syncthreads();

        uint32_t sA = sb + (uint32_t)(kt % NSTAGE) * STAGE_BYTES;
        uint32_t sB = sA + SLOT_BYTES;
#pragma unroll
        for (int kblk = 0; kblk < 4; ++kblk) {
            uint32_t afr[4][4];
            uint32_t bfr[4][2];
            if (TA == 0) {
#pragma unroll
                for (int mi = 0; mi < 4; ++mi)
                    ldsm_x4(afr[mi], sA + aRel + (uint32_t)(mi * 2304 + kblk * 32));
            } else {
#pragma unroll
                for (int mi = 0; mi < 4; ++mi) {
                    uint32_t base = sA + aRel + (uint32_t)(kblk * 4352 + mi * 64);
                    afr[mi][0] = lds32(base);
                    afr[mi][1] = lds32(base + 32);
                    afr[mi][2] = lds32(base + 2176);
                    afr[mi][3] = lds32(base + 2208);
                }
            }
            if (TB == 0) {
#pragma unroll
                for (int p = 0; p < 2; ++p) {
                    uint32_t t4[4];
                    ldsm_x4(t4, sB + bRel + (uint32_t)(p * 2304 + kblk * 32));
                    bfr[2 * p + 0][0] = t4[0]; bfr[2 * p + 0][1] = t4[1];
                    bfr[2 * p + 1][0] = t4[2]; bfr[2 * p + 1][1] = t4[3];
                }
            } else {
#pragma unroll
                for (int ni = 0; ni < 4; ++ni) {
                    uint32_t base = sB + bRel + (uint32_t)(kblk * 4352 + ni * 32);
                    bfr[ni][0] = lds32(base);
                    bfr[ni][1] = lds32(base + 2176);
                }
            }
#pragma unroll
            for (int mi = 0; mi < 4; ++mi)
#pragma unroll
                for (int ni = 0; ni < 4; ++ni)
                    mma_tf32(acc[mi][ni], afr[mi], bfr[ni]);
        }
        __syncthreads();
    }

    // ---------------- epilogue ----------------
#pragma unroll
    for (int mi = 0; mi < 4; ++mi) {
        int rbase = m0 + wm * 64 + mi * 16 + tr;
#pragma unroll
        for (int half = 0; half < 2; ++half) {
            size_t row = (size_t)rbase + half * 8;
            float dinv = 0.0f;
            if (EPI == EPI_ATT) dinv = 1.0f / P3[row];
#pragma unroll
            for (int ni = 0; ni < 4; ++ni) {
                int col = n0 + wn * 32 + ni * 8 + tq * 2;
                float c0 = acc[mi][ni][half * 2 + 0];
                float c1 = acc[mi][ni][half * 2 + 1];
                float* dst = C + row * (size_t)ldc + col;
                float2 o;
                if (EPI == EPI_NONE) {
                    o.x = c0; o.y = c1;
                } else if (EPI == EPI_BIAS) {
                    float2 bv = *(const float2*)(P1 + col);
                    o.x = c0 + bv.x; o.y = c1 + bv.y;
                } else {
                    float2 vv = *(const float2*)(P1 + row * HID + col);
                    float2 hh = *(const float2*)(P2 + row * HID + col);
                    o.x = ((c0 + 4096.0f * vv.x) * dinv + hh.x) * 0.5f;
                    o.y = ((c1 + 4096.0f * vv.y) * dinv + hh.y) * 0.5f;
                }
                if (RND) { o.x = roundtf(o.x); o.y = roundtf(o.y); }
                *(float2*)dst = o;
            }
        }
    }
}

// ================= elementwise kernels =================
__device__ __forceinline__ float wred(float v) {
#pragma unroll
    for (int o = 16; o; o >>= 1) v += __shfl_xor_sync(0xffffffffu, v, o);
    return v;
}

__global__ void round_copy(const float4* __restrict__ in, float4* __restrict__ out, int n4) {
    int i = blockIdx.x * blockDim.x + threadIdx.x;
    if (i < n4) {
        float4 v = in[i];
        v.x = roundtf(v.x); v.y = roundtf(v.y);
        v.z = roundtf(v.z); v.w = roundtf(v.w);
        out[i] = v;
    }
}

// LayerNorm + ReLU; rnd: round output to tf32-representable fp32
__global__ void ln_relu(const float* __restrict__ in, float* __restrict__ out,
                        const float* __restrict__ g, const float* __restrict__ b, int rnd) {
    size_t warp = ((size_t)blockIdx.x * blockDim.x + threadIdx.x) >> 5;
    int lane = threadIdx.x & 31;
    const float4* src = (const float4*)(in + warp * HID);
    float4 v[4];
    float s = 0.0f, s2 = 0.0f;
#pragma unroll
    for (int c = 0; c < 4; ++c) {
        v[c] = src[lane + 32 * c];
        s  += v[c].x + v[c].y + v[c].z + v[c].w;
        s2 += v[c].x * v[c].x + v[c].y * v[c].y + v[c].z * v[c].z + v[c].w * v[c].w;
    }
    s = wred(s); s2 = wred(s2);
    float mu = s * (1.0f / HID);
    float var = s2 * (1.0f / HID) - mu * mu;
    float rstd = rsqrtf(var + LN_EPS);
    float4* dst = (float4*)(out + warp * HID);
#pragma unroll
    for (int c = 0; c < 4; ++c) {
        int i4 = lane + 32 * c;
        float4 gg = ((const float4*)g)[i4];
        float4 bb = ((const float4*)b)[i4];
        float4 o;
        o.x = fmaxf(0.0f, (v[c].x - mu) * rstd * gg.x + bb.x);
        o.y = fmaxf(0.0f, (v[c].y - mu) * rstd * gg.y + bb.y);
        o.z = fmaxf(0.0f, (v[c].z - mu) * rstd * gg.z + bb.z);
        o.w = fmaxf(0.0f, (v[c].w - mu) * rstd * gg.w + bb.w);
        if (rnd) {
            o.x = roundtf(o.x); o.y = roundtf(o.y);
            o.z = roundtf(o.z); o.w = roundtf(o.w);
        }
        dst[i4] = o;
    }
}

// q/k: replace exact zeros with eps, L2-normalize, round to tf32
__global__ void norm_qk(float* __restrict__ X) {
    size_t warp = ((size_t)blockIdx.x * blockDim.x + threadIdx.x) >> 5;
    int lane = threadIdx.x & 31;
    float4* p = (float4*)(X + warp * HID);
    float4 v[4];
    float s2 = 0.0f;
#pragma unroll
    for (int c = 0; c < 4; ++c) {
        v[c] = p[lane + 32 * c];
        if (v[c].x == 0.0f) v[c].x = QK_EPS;
        if (v[c].y == 0.0f) v[c].y = QK_EPS;
        if (v[c].z == 0.0f) v[c].z = QK_EPS;
        if (v[c].w == 0.0f) v[c].w = QK_EPS;
        s2 += v[c].x * v[c].x + v[c].y * v[c].y + v[c].z * v[c].z + v[c].w * v[c].w;
    }
    s2 = wred(s2);
    float rn = rsqrtf(s2);
#pragma unroll
    for (int c = 0; c < 4; ++c) {
        v[c].x = roundtf(v[c].x * rn); v[c].y = roundtf(v[c].y * rn);
        v[c].z = roundtf(v[c].z * rn); v[c].w = roundtf(v[c].w * rn);
        p[lane + 32 * c] = v[c];
    }
}

__global__ void kvs_reduce(const float* __restrict__ Part, float* __restrict__ KVS) {
    size_t o = (size_t)blockIdx.x * blockDim.x + threadIdx.x;   // 16*512*512
    size_t graph = o >> 18;
    size_t r = o & ((1u << 18) - 1);
    float s = 0.0f;
#pragma unroll
    for (int sp = 0; sp < SK; ++sp)
        s += Part[((size_t)sp * NGRAPH + graph) * HID * HID + r];
    KVS[o] = roundtf(s);
}

__global__ void ksum_part(const float* __restrict__ Kmat, float* __restrict__ Part) {
    int graph = blockIdx.x >> 3, chunk = blockIdx.x & 7;
    int ch = threadIdx.x;
    size_t base = ((size_t)graph * NNODES + (size_t)chunk * (NNODES / SPLITS)) * HID + ch;
    float s = 0.0f;
#pragma unroll 8
    for (int r = 0; r < NNODES / SPLITS; ++r)
        s += Kmat[base + (size_t)r * HID];
    Part[(size_t)blockIdx.x * HID + ch] = s;
}

__global__ void ksum_reduce(const float* __restrict__ Part, float* __restrict__ KS) {
    int idx = blockIdx.x * blockDim.x + threadIdx.x;
    int graph = idx >> 9, ch = idx & 511;
    float s = 0.0f;
#pragma unroll
    for (int c = 0; c < SPLITS; ++c)
        s += Part[((size_t)(graph * SPLITS + c)) * HID + ch];
    KS[idx] = s;
}

__global__ void denom_kernel(const float* __restrict__ Q, const float* __restrict__ KS,
                             float* __restrict__ den) {
    size_t warp = ((size_t)blockIdx.x * blockDim.x + threadIdx.x) >> 5;
    int lane = threadIdx.x & 31;
    int graph = (int)(warp >> 12);
    const float4* qp = (const float4*)(Q + warp * HID);
    const float4* kp = (const float4*)(KS + (size_t)graph * HID);
    float s = 0.0f;
#pragma unroll
    for (int c = 0; c < 4; ++c) {
        float4 a = qp[lane + 32 * c];
        float4 b = kp[lane + 32 * c];
        s += a.x * b.x + a.y * b.y + a.z * b.z + a.w * b.w;
    }
    s = wred(s);
    if (lane == 0) den[warp] = s + (float)NNODES;
}

// ================= launch =================
extern "C" void kernel_launch(void* const* d_in, const int* in_sizes, int n_in,
                              void* d_out, int out_size) {
    const float* x     = (const float*)d_in[0];
    const float* fc0_w = (const float*)d_in[1];
    const float* fc0_b = (const float*)d_in[2];
    const float* ln_g[3] = { (const float*)d_in[3], (const float*)d_in[8],  (const float*)d_in[13] };
    const float* ln_b[3] = { (const float*)d_in[4], (const float*)d_in[9],  (const float*)d_in[14] };
    const float* qw[2] = { (const float*)d_in[5],  (const float*)d_in[10] };
    const float* kw[2] = { (const float*)d_in[6],  (const float*)d_in[11] };
    const float* vw[2] = { (const float*)d_in[7],  (const float*)d_in[12] };
    float* out = (float*)d_out;
    // batch = repeat(arange(16), 4096): argsort and rev_perm are identities.

    float *h, *q, *k, *v, *t, *xr, *wr, *kvp, *kvs, *ksp, *ks, *den;
    cudaGetSymbolAddress((void**)&h,   g_h);
    cudaGetSymbolAddress((void**)&q,   g_q);
    cudaGetSymbolAddress((void**)&k,   g_k);
    cudaGetSymbolAddress((void**)&v,   g_v);
    cudaGetSymbolAddress((void**)&t,   g_t);
    cudaGetSymbolAddress((void**)&xr,  g_xr);
    cudaGetSymbolAddress((void**)&wr,  g_wr);
    cudaGetSymbolAddress((void**)&kvp, g_kvp);
    cudaGetSymbolAddress((void**)&kvs, g_kvs);
    cudaGetSymbolAddress((void**)&ksp, g_ksp);
    cudaGetSymbolAddress((void**)&ks,  g_ks);
    cudaGetSymbolAddress((void**)&den, g_den);

    cudaFuncSetAttribute((const void*)mm_tc<0,0,EPI_BIAS,0>,
                         cudaFuncAttributeMaxDynamicSharedMemorySize, SMEM_BYTES);
    cudaFuncSetAttribute((const void*)mm_tc<0,0,EPI_NONE,0>,
                         cudaFuncAttributeMaxDynamicSharedMemorySize, SMEM_BYTES);
    cudaFuncSetAttribute((const void*)mm_tc<0,0,EPI_NONE,1>,
                         cudaFuncAttributeMaxDynamicSharedMemorySize, SMEM_BYTES);
    cudaFuncSetAttribute((const void*)mm_tc<1,1,EPI_NONE,0>,
                         cudaFuncAttributeMaxDynamicSharedMemorySize, SMEM_BYTES);
    cudaFuncSetAttribute((const void*)mm_tc<0,1,EPI_ATT,0>,
                         cudaFuncAttributeMaxDynamicSharedMemorySize, SMEM_BYTES);

    // rounded weight scratch layout
    float* wr_fc0 = wr;
    float* wr_qkv[2][3];
    {
        size_t off = (size_t)HID * INCH;
        for (int l = 0; l < 2; ++l)
            for (int j = 0; j < 3; ++j) {
                wr_qkv[l][j] = wr + off;
                off += (size_t)HID * HID;
            }
    }

    // pre-round x and all weights to tf32-representable fp32
    round_copy<<<(TOTAL * INCH / 4 + 255) / 256, 256>>>((const float4*)x, (float4*)xr, TOTAL * INCH / 4);
    round_copy<<<(HID * INCH / 4 + 255) / 256, 256>>>((const float4*)fc0_w, (float4*)wr_fc0, HID * INCH / 4);
    const float* wsrc[2][3] = { { qw[0], kw[0], vw[0] }, { qw[1], kw[1], vw[1] } };
    for (int l = 0; l < 2; ++l)
        for (int j = 0; j < 3; ++j)
            round_copy<<<(HID * HID / 4 + 255) / 256, 256>>>(
                (const float4*)wsrc[l][j], (float4*)wr_qkv[l][j], HID * HID / 4);

    const dim3 big_grid(HID / BN, TOTAL / BM, 1);   // (4, 512)
    const int  row_blocks = TOTAL / 8;

    // h = relu(LN(x @ fc0_w^T + b))   [h rounded to tf32]
    mm_tc<0,0,EPI_BIAS,0><<<big_grid, 256, SMEM_BYTES>>>(
        xr, wr_fc0, t, fc0_b, nullptr, nullptr, INCH, INCH, INCH, HID,
        0, 0, 0, 0, 0, 0, 0);
    ln_relu<<<row_blocks, 256>>>(t, h, ln_g[0], ln_b[0], 1);

    for (int l = 0; l < 2; ++l) {
        float* dst = (l == 1) ? out : h;
        mm_tc<0,0,EPI_NONE,0><<<big_grid, 256, SMEM_BYTES>>>(
            h, wr_qkv[l][0], q, nullptr, nullptr, nullptr, HID, HID, HID, HID,
            0, 0, 0, 0, 0, 0, 0);
        mm_tc<0,0,EPI_NONE,0><<<big_grid, 256, SMEM_BYTES>>>(
            h, wr_qkv[l][1], k, nullptr, nullptr, nullptr, HID, HID, HID, HID,
            0, 0, 0, 0, 0, 0, 0);
        mm_tc<0,0,EPI_NONE,1><<<big_grid, 256, SMEM_BYTES>>>(      // v rounded
            h, wr_qkv[l][2], v, nullptr, nullptr, nullptr, HID, HID, HID, HID,
            0, 0, 0, 0, 0, 0, 0);
        norm_qk<<<row_blocks, 256>>>(q);
        norm_qk<<<row_blocks, 256>>>(k);
        // kvp[split][g][m,d] = sum_{n in split} k[g,n,m] * v[g,n,d]
        mm_tc<1,1,EPI_NONE,0><<<dim3(HID / BN, HID / BM, NGRAPH * SK), 256, SMEM_BYTES>>>(
            k, v, kvp, nullptr, nullptr, nullptr, NNODES / SK, HID, HID, HID,
            (size_t)NNODES * HID, (size_t)(NNODES / SK) * HID,
            (size_t)NNODES * HID, (size_t)(NNODES / SK) * HID,
            (size_t)HID * HID, (size_t)NGRAPH * HID * HID, 0);
        kvs_reduce<<<(NGRAPH * HID * HID) / 256, 256>>>(kvp, kvs);
        ksum_part<<<NGRAPH * SPLITS, HID>>>(k, ksp);
        ksum_reduce<<<(NGRAPH * HID) / 256, 256>>>(ksp, ks);
        denom_kernel<<<row_blocks, 256>>>(q, ks, den);
        // t = ((q @ kvs + N*v)/den + h)/2
        mm_tc<0,1,EPI_ATT,0><<<dim3(HID / BN, NNODES / BM, NGRAPH), 256, SMEM_BYTES>>>(
            q, kvs, t, v, h, den, HID, HID, HID, HID,
            0, 0, (size_t)HID * HID, 0, 0, 0, NNODES);
        ln_relu<<<row_blocks, 256>>>(t, dst, ln_g[l + 1], ln_b[l + 1], (l == 0) ? 1 : 0);
    }
}